// round 10
// baseline (speedup 1.0000x reference)
#include <cuda_runtime.h>
#include <cuda_fp16.h>

#define N_NODES 50000
#define N_EDGES 800000
#define D_FEAT  64
#define WARPS_PER_BLOCK 8
#define ROWS_PER_BLOCK (WARPS_PER_BLOCK * 4)   // quarter-warp per row
#define CONV_THREADS (N_NODES * D_FEAT / 8)    // 400000

// Precomputed CSR row pointers.
__device__ int g_row_ptr[N_NODES + 1];
// fp16 copy of embeds: one 128B line per row. 6.4MB, L2-resident.
__device__ __half2 g_emb_h[N_NODES * D_FEAT / 2];
// Fused (col, val-bits) per edge: one LDG.64 fetches both.
__device__ int2 g_meta[N_EDGES];

// Fused prep: row_ptr scatter build + meta pack + fp32->fp16 embed convert.
__global__ __launch_bounds__(256)
void prep_kernel(const int* __restrict__ row_idx,
                 const int* __restrict__ col_idx,
                 const float* __restrict__ vals,
                 const float* __restrict__ embeds) {
    const int t = blockIdx.x * blockDim.x + threadIdx.x;

    if (t <= N_EDGES) {
        if (t == 0) {
            const int r1 = __ldg(row_idx + 0);
            for (int r = 0; r <= r1; r++) g_row_ptr[r] = 0;
        } else {
            const int r0 = __ldg(row_idx + t - 1);
            const int r1 = (t < N_EDGES) ? __ldg(row_idx + t) : N_NODES;
            for (int r = r0 + 1; r <= r1; r++) g_row_ptr[r] = t;
        }
        if (t < N_EDGES)
            g_meta[t] = make_int2(__ldg(col_idx + t),
                                  __float_as_int(__ldg(vals + t)));
    }

    if (t < CONV_THREADS) {
        const float4* e4 = reinterpret_cast<const float4*>(embeds);
        const float4 a = __ldg(e4 + 2 * t);
        const float4 b = __ldg(e4 + 2 * t + 1);
        __half2* dst = g_emb_h + 4 * t;
        dst[0] = __float22half2_rn(make_float2(a.x, a.y));
        dst[1] = __float22half2_rn(make_float2(a.z, a.w));
        dst[2] = __float22half2_rn(make_float2(b.x, b.y));
        dst[3] = __float22half2_rn(make_float2(b.z, b.w));
    }
}

// Packed f32x2 helpers.
__device__ __forceinline__ unsigned long long pk2(float lo, float hi) {
    unsigned long long r;
    asm("mov.b64 %0, {%1, %2};" : "=l"(r) : "f"(lo), "f"(hi));
    return r;
}
__device__ __forceinline__ void ffma2(unsigned long long& acc,
                                      unsigned long long x,
                                      unsigned long long v) {
    asm("fma.rn.f32x2 %0, %1, %2, %3;" : "=l"(acc) : "l"(x), "l"(v), "l"(acc));
}
__device__ __forceinline__ float2 unpk2(unsigned long long p) {
    float2 f;
    asm("mov.b64 {%0, %1}, %2;" : "=f"(f.x), "=f"(f.y) : "l"(p));
    return f;
}

// Kernel B: QUARTER-warp per row. 8 lanes x uint4 = the full 128B fp16 row;
// each lane owns halves [8q..8q+7] -> lane-local accumulators, NO cross-lane
// reduction, direct coalesced store. Main loop: one edge-pair per iteration
// (2 independent gathers, MLP=2), meta via single LDG.64 per edge.
__global__ __launch_bounds__(WARPS_PER_BLOCK * 32)
void gcn_spmm_kernel(float* __restrict__ out) {
    const int tid  = threadIdx.x;
    const int lane = tid & 31;
    const int q    = lane & 7;                       // dim slice
    const int row  = blockIdx.x * ROWS_PER_BLOCK + (tid >> 3);
    if (row >= N_NODES) return;

    const int start = __ldg(&g_row_ptr[row]);
    const int end   = __ldg(&g_row_ptr[row + 1]);

    const uint4* __restrict__ emb16 = reinterpret_cast<const uint4*>(g_emb_h);

    unsigned long long A0 = 0ull, A1 = 0ull, A2 = 0ull, A3 = 0ull;

    int e = start;
    // Main: unguarded edge pairs, 2 independent gathers in flight.
    for (; e + 2 <= end; e += 2) {
        const int2 m0 = __ldg(&g_meta[e]);
        const int2 m1 = __ldg(&g_meta[e + 1]);
        const uint4 x0 = __ldg(emb16 + (size_t)m0.x * 8 + q);
        const uint4 x1 = __ldg(emb16 + (size_t)m1.x * 8 + q);
        const float v0 = __int_as_float(m0.y);
        const float v1 = __int_as_float(m1.y);
        const unsigned long long vv0 = pk2(v0, v0);
        const unsigned long long vv1 = pk2(v1, v1);

        float2 f;
        f = __half22float2(*reinterpret_cast<const __half2*>(&x0.x));
        ffma2(A0, pk2(f.x, f.y), vv0);
        f = __half22float2(*reinterpret_cast<const __half2*>(&x0.y));
        ffma2(A1, pk2(f.x, f.y), vv0);
        f = __half22float2(*reinterpret_cast<const __half2*>(&x0.z));
        ffma2(A2, pk2(f.x, f.y), vv0);
        f = __half22float2(*reinterpret_cast<const __half2*>(&x0.w));
        ffma2(A3, pk2(f.x, f.y), vv0);

        f = __half22float2(*reinterpret_cast<const __half2*>(&x1.x));
        ffma2(A0, pk2(f.x, f.y), vv1);
        f = __half22float2(*reinterpret_cast<const __half2*>(&x1.y));
        ffma2(A1, pk2(f.x, f.y), vv1);
        f = __half22float2(*reinterpret_cast<const __half2*>(&x1.z));
        ffma2(A2, pk2(f.x, f.y), vv1);
        f = __half22float2(*reinterpret_cast<const __half2*>(&x1.w));
        ffma2(A3, pk2(f.x, f.y), vv1);
    }
    // Odd trailing edge.
    if (e < end) {
        const int2 m0 = __ldg(&g_meta[e]);
        const uint4 x0 = __ldg(emb16 + (size_t)m0.x * 8 + q);
        const float v0 = __int_as_float(m0.y);
        const unsigned long long vv0 = pk2(v0, v0);
        float2 f;
        f = __half22float2(*reinterpret_cast<const __half2*>(&x0.x));
        ffma2(A0, pk2(f.x, f.y), vv0);
        f = __half22float2(*reinterpret_cast<const __half2*>(&x0.y));
        ffma2(A1, pk2(f.x, f.y), vv0);
        f = __half22float2(*reinterpret_cast<const __half2*>(&x0.z));
        ffma2(A2, pk2(f.x, f.y), vv0);
        f = __half22float2(*reinterpret_cast<const __half2*>(&x0.w));
        ffma2(A3, pk2(f.x, f.y), vv0);
    }

    // Direct store: lane q writes floats [8q..8q+7] of the row. No shuffles.
    const float2 u0 = unpk2(A0), u1 = unpk2(A1);
    const float2 u2 = unpk2(A2), u3 = unpk2(A3);
    float4* o4 = reinterpret_cast<float4*>(out + (size_t)row * D_FEAT + q * 8);
    o4[0] = make_float4(u0.x, u0.y, u1.x, u1.y);
    o4[1] = make_float4(u2.x, u2.y, u3.x, u3.y);
}

extern "C" void kernel_launch(void* const* d_in, const int* in_sizes, int n_in,
                              void* d_out, int out_size) {
    const int*   row_idx = (const int*)  d_in[0];
    const int*   col_idx = (const int*)  d_in[1];
    const float* vals    = (const float*)d_in[2];
    const float* embeds  = (const float*)d_in[3];
    float*       out     = (float*)d_out;

    prep_kernel<<<(N_EDGES + 1 + 255) / 256, 256>>>(row_idx, col_idx, vals,
                                                    embeds);

    const int blocks = (N_NODES + ROWS_PER_BLOCK - 1) / ROWS_PER_BLOCK; // 1563
    gcn_spmm_kernel<<<blocks, WARPS_PER_BLOCK * 32>>>(out);
}

// round 11
// speedup vs baseline: 1.0490x; 1.0490x over previous
#include <cuda_runtime.h>
#include <cuda_fp16.h>

#define N_NODES 50000
#define N_EDGES 800000
#define D_FEAT  64
#define WARPS_PER_BLOCK 8
#define ROWS_PER_BLOCK (WARPS_PER_BLOCK * 4)   // quarter-warp per row
#define CONV_THREADS (N_NODES * D_FEAT / 8)    // 400000

// Precomputed CSR row pointers.
__device__ int g_row_ptr[N_NODES + 1];
// fp16 copy of embeds: one 128B line per row. 6.4MB, L2-resident.
__device__ __half2 g_emb_h[N_NODES * D_FEAT / 2];

// Fused prep: O(E) scatter row_ptr build + fp32->fp16 embed convert.
__global__ __launch_bounds__(256)
void prep_kernel(const int* __restrict__ row_idx,
                 const float* __restrict__ embeds) {
    const int t = blockIdx.x * blockDim.x + threadIdx.x;

    if (t <= N_EDGES) {
        if (t == 0) {
            const int r1 = __ldg(row_idx + 0);
            for (int r = 0; r <= r1; r++) g_row_ptr[r] = 0;
        } else {
            const int r0 = __ldg(row_idx + t - 1);
            const int r1 = (t < N_EDGES) ? __ldg(row_idx + t) : N_NODES;
            for (int r = r0 + 1; r <= r1; r++) g_row_ptr[r] = t;
        }
    }

    if (t < CONV_THREADS) {
        const float4* e4 = reinterpret_cast<const float4*>(embeds);
        const float4 a = __ldg(e4 + 2 * t);
        const float4 b = __ldg(e4 + 2 * t + 1);
        __half2* dst = g_emb_h + 4 * t;
        dst[0] = __float22half2_rn(make_float2(a.x, a.y));
        dst[1] = __float22half2_rn(make_float2(a.z, a.w));
        dst[2] = __float22half2_rn(make_float2(b.x, b.y));
        dst[3] = __float22half2_rn(make_float2(b.z, b.w));
    }
}

// Packed f32x2 helpers.
__device__ __forceinline__ unsigned long long pk2(float lo, float hi) {
    unsigned long long r;
    asm("mov.b64 %0, {%1, %2};" : "=l"(r) : "f"(lo), "f"(hi));
    return r;
}
__device__ __forceinline__ void ffma2(unsigned long long& acc,
                                      unsigned long long x,
                                      unsigned long long v) {
    asm("fma.rn.f32x2 %0, %1, %2, %3;" : "=l"(acc) : "l"(x), "l"(v), "l"(acc));
}
__device__ __forceinline__ float2 unpk2(unsigned long long p) {
    float2 f;
    asm("mov.b64 {%0, %1}, %2;" : "=f"(f.x), "=f"(f.y) : "l"(p));
    return f;
}

// Accumulate one fp16 embed row slice (uint4 = 8 halves) times v.
__device__ __forceinline__ void acc_edge(unsigned long long& A0,
                                         unsigned long long& A1,
                                         unsigned long long& A2,
                                         unsigned long long& A3,
                                         uint4 x, float v) {
    const unsigned long long vv = pk2(v, v);
    float2 f;
    f = __half22float2(*reinterpret_cast<const __half2*>(&x.x));
    ffma2(A0, pk2(f.x, f.y), vv);
    f = __half22float2(*reinterpret_cast<const __half2*>(&x.y));
    ffma2(A1, pk2(f.x, f.y), vv);
    f = __half22float2(*reinterpret_cast<const __half2*>(&x.z));
    ffma2(A2, pk2(f.x, f.y), vv);
    f = __half22float2(*reinterpret_cast<const __half2*>(&x.w));
    ffma2(A3, pk2(f.x, f.y), vv);
}

// Kernel B: QUARTER-warp per row (8 lanes x uint4 = full 128B fp16 row),
// lane-local accumulators, no cross-lane reduction. Main loop: 4 edges per
// iteration, 4 independent gathers in flight (MLP=4).
__global__ __launch_bounds__(WARPS_PER_BLOCK * 32)
void gcn_spmm_kernel(const int* __restrict__ col_idx,
                     const float* __restrict__ vals,
                     float* __restrict__ out) {
    const int tid  = threadIdx.x;
    const int lane = tid & 31;
    const int q    = lane & 7;                       // dim slice
    const int row  = blockIdx.x * ROWS_PER_BLOCK + (tid >> 3);
    if (row >= N_NODES) return;

    const int start = __ldg(&g_row_ptr[row]);
    const int end   = __ldg(&g_row_ptr[row + 1]);

    const uint4* __restrict__ emb16 = reinterpret_cast<const uint4*>(g_emb_h);

    unsigned long long A0 = 0ull, A1 = 0ull, A2 = 0ull, A3 = 0ull;

    int e = start;
    // Main: unguarded 4-edge chunks, 4 independent gathers in flight.
    for (; e + 4 <= end; e += 4) {
        const int c0 = __ldg(col_idx + e);
        const int c1 = __ldg(col_idx + e + 1);
        const int c2 = __ldg(col_idx + e + 2);
        const int c3 = __ldg(col_idx + e + 3);
        const uint4 x0 = __ldg(emb16 + (size_t)c0 * 8 + q);
        const uint4 x1 = __ldg(emb16 + (size_t)c1 * 8 + q);
        const uint4 x2 = __ldg(emb16 + (size_t)c2 * 8 + q);
        const uint4 x3 = __ldg(emb16 + (size_t)c3 * 8 + q);
        const float v0 = __ldg(vals + e);
        const float v1 = __ldg(vals + e + 1);
        const float v2 = __ldg(vals + e + 2);
        const float v3 = __ldg(vals + e + 3);

        acc_edge(A0, A1, A2, A3, x0, v0);
        acc_edge(A0, A1, A2, A3, x1, v1);
        acc_edge(A0, A1, A2, A3, x2, v2);
        acc_edge(A0, A1, A2, A3, x3, v3);
    }
    // Tail: <= 3 edges.
    for (; e < end; e++) {
        const int c0 = __ldg(col_idx + e);
        const uint4 x0 = __ldg(emb16 + (size_t)c0 * 8 + q);
        const float v0 = __ldg(vals + e);
        acc_edge(A0, A1, A2, A3, x0, v0);
    }

    // Direct store: lane q writes floats [8q..8q+7] of the row. No shuffles.
    const float2 u0 = unpk2(A0), u1 = unpk2(A1);
    const float2 u2 = unpk2(A2), u3 = unpk2(A3);
    float4* o4 = reinterpret_cast<float4*>(out + (size_t)row * D_FEAT + q * 8);
    o4[0] = make_float4(u0.x, u0.y, u1.x, u1.y);
    o4[1] = make_float4(u2.x, u2.y, u3.x, u3.y);
}

extern "C" void kernel_launch(void* const* d_in, const int* in_sizes, int n_in,
                              void* d_out, int out_size) {
    const int*   row_idx = (const int*)  d_in[0];
    const int*   col_idx = (const int*)  d_in[1];
    const float* vals    = (const float*)d_in[2];
    const float* embeds  = (const float*)d_in[3];
    float*       out     = (float*)d_out;

    prep_kernel<<<(N_EDGES + 1 + 255) / 256, 256>>>(row_idx, embeds);

    const int blocks = (N_NODES + ROWS_PER_BLOCK - 1) / ROWS_PER_BLOCK; // 1563
    gcn_spmm_kernel<<<blocks, WARPS_PER_BLOCK * 32>>>(col_idx, vals, out);
}